// round 12
// baseline (speedup 1.0000x reference)
#include <cuda_runtime.h>
#include <cuda_fp16.h>
#include <cstdint>

#define KC 1024
#define DC 64
#define NV 131072
#define TM 128      // rows per CTA
#define NT 256      // threads (8 warps x 16 rows)

// ---------------- scratch ----------------
__device__ __align__(16) float g_esq[KC];
__device__ __align__(16) float g_counts[KC];
__device__ __align__(16) float g_sums[KC * DC];
__device__ float g_loss[1];
__device__ __align__(16) float g_csa[KC];
__device__ __align__(16) __half g_Ehi[KC * DC];   // NEGATED e hi
__device__ __align__(16) __half g_Elo[KC * DC];   // NEGATED e lo

// ---------------- PTX helpers (arch-neutral) ----------------
__device__ __forceinline__ void mma16816(float* a,
                                         uint32_t a0, uint32_t a1, uint32_t a2, uint32_t a3,
                                         uint32_t b0, uint32_t b1) {
    asm volatile("mma.sync.aligned.m16n8k16.row.col.f32.f16.f16.f32 "
                 "{%0,%1,%2,%3}, {%4,%5,%6,%7}, {%8,%9}, {%0,%1,%2,%3};"
                 : "+f"(a[0]), "+f"(a[1]), "+f"(a[2]), "+f"(a[3])
                 : "r"(a0), "r"(a1), "r"(a2), "r"(a3), "r"(b0), "r"(b1));
}
__device__ __forceinline__ void ldsm4(uint32_t& r0, uint32_t& r1, uint32_t& r2, uint32_t& r3,
                                      uint32_t addr) {
    asm volatile("ldmatrix.sync.aligned.m8n8.x4.shared.b16 {%0,%1,%2,%3}, [%4];"
                 : "=r"(r0), "=r"(r1), "=r"(r2), "=r"(r3) : "r"(addr));
}
__device__ __forceinline__ uint32_t smem_u32(const void* p) {
    uint32_t a;
    asm("{ .reg .u64 t; cvta.to.shared.u64 t, %1; cvt.u32.u64 %0, t; }" : "=r"(a) : "l"(p));
    return a;
}

// ---------------- prep kernels ----------------
__global__ void vq_zero() {
    int i = blockIdx.x * blockDim.x + threadIdx.x;
    if (i < KC * DC / 4) {
        ((float4*)g_sums)[i] = make_float4(0.f, 0.f, 0.f, 0.f);
    } else if (i < KC * DC / 4 + KC) {
        g_counts[i - KC * DC / 4] = 0.f;
    } else if (i == KC * DC / 4 + KC) {
        g_loss[0] = 0.f;
    }
}

__global__ void vq_esq(const float* __restrict__ E) {
    int k = blockIdx.x * blockDim.x + threadIdx.x;
    if (k < KC) {
        const float4* r = (const float4*)(E + (size_t)k * DC);
        float s = 0.f;
#pragma unroll
        for (int q = 0; q < DC / 4; q++) {
            float4 v = r[q];
            s = fmaf(v.x, v.x, s); s = fmaf(v.y, v.y, s);
            s = fmaf(v.z, v.z, s); s = fmaf(v.w, v.w, s);
        }
        g_esq[k] = s;
    }
}

// split NEGATED E into fp16 hi/lo (so MMA accumulates -dot on top of esq/2 init)
__global__ void vq_esplit(const float* __restrict__ E) {
    int i4 = blockIdx.x * blockDim.x + threadIdx.x;   // < KC*DC/4
    float4 v = ((const float4*)E)[i4];
    float n0 = -v.x, n1 = -v.y, n2 = -v.z, n3 = -v.w;
    __half h0 = __float2half_rn(n0), h1 = __float2half_rn(n1);
    __half h2 = __float2half_rn(n2), h3 = __float2half_rn(n3);
    float l0 = n0 - __half2float(h0), l1 = n1 - __half2float(h1);
    float l2 = n2 - __half2float(h2), l3 = n3 - __half2float(h3);
    __half2* H = (__half2*)g_Ehi;
    __half2* L = (__half2*)g_Elo;
    H[i4 * 2] = __halves2half2(h0, h1);
    H[i4 * 2 + 1] = __halves2half2(h2, h3);
    L[i4 * 2] = __halves2half2(__float2half_rn(l0), __float2half_rn(l1));
    L[i4 * 2 + 1] = __halves2half2(__float2half_rn(l2), __float2half_rn(l3));
}

// ---------------- smem layout (bytes) ----------------
#define ROWB 144                               // 72 fp16 per row: conflict-free ldmatrix
#define SM_XHI 0                               // 128 * 144 = 18432
#define SM_EB  (TM * ROWB)                     // 18432
#define EBUF_SPLIT (64 * ROWB)                 // 9216 (one split: 64 codes)
#define EBUF_FULL (2 * EBUF_SPLIT)             // 18432 (hi + lo)
#define SM_ESQ (SM_EB + 2 * EBUF_FULL)         // 55296   esq*0.5 per code
#define SM_RED (SM_ESQ + KC * 4)               // 59392
#define SM_TOTB (SM_RED + TM * 12)             // 60928

// ---------------- main kernel ----------------
extern "C" __global__ void __launch_bounds__(NT, 2)
vq_main_mma(const float* __restrict__ X, const float* __restrict__ E,
            float* __restrict__ oZ, float* __restrict__ oArg, float* __restrict__ oMin) {
    extern __shared__ char sm[];
    __half* Xhi = (__half*)(sm + SM_XHI);
    float* esq2_s = (float*)(sm + SM_ESQ);    // esq * 0.5
    float* rbest = (float*)(sm + SM_RED);
    float* rsec = rbest + TM;
    int* ridx = (int*)(rsec + TM);

    const int tid = threadIdx.x;
    const int wid = tid >> 5, lane = tid & 31;
    const int g = lane >> 2, c4 = lane & 3;
    const int rowb = wid * 16;
    const uint32_t sbase = smem_u32(sm);

    for (int i = tid; i < KC; i += NT) esq2_s[i] = 0.5f * g_esq[i];

    // X tile: load fp32, keep fp16-hi only (lo term folded into rescue margin)
    const float4* Xg4 = (const float4*)(X + (size_t)blockIdx.x * TM * DC);
#pragma unroll
    for (int j = 0; j < 8; j++) {
        int i4 = tid + NT * j;
        float4 v = Xg4[i4];
        int row = i4 >> 4, col = (i4 & 15) * 4;
        __half2* dst = (__half2*)(Xhi + row * 72 + col);
        dst[0] = __halves2half2(__float2half_rn(v.x), __float2half_rn(v.y));
        dst[1] = __halves2half2(__float2half_rn(v.z), __float2half_rn(v.w));
    }
    __syncthreads();

    // A fragments (fp16 hi) held in registers for the whole kernel
    uint32_t ah[4][4];
#pragma unroll
    for (int k = 0; k < 4; k++) {
        int cb = k * 16 + c4 * 2;
        ah[k][0] = *(const uint32_t*)(Xhi + (rowb + g) * 72 + cb);
        ah[k][1] = *(const uint32_t*)(Xhi + (rowb + 8 + g) * 72 + cb);
        ah[k][2] = *(const uint32_t*)(Xhi + (rowb + g) * 72 + cb + 8);
        ah[k][3] = *(const uint32_t*)(Xhi + (rowb + 8 + g) * 72 + cb + 8);
    }

    // E chunk copy (64 codes, hi+lo) into buffer b
#define COPY_E(ch, b) do {                                                        \
        const uint4* shh = (const uint4*)g_Ehi + (ch) * 512;                      \
        const uint4* sll = (const uint4*)g_Elo + (ch) * 512;                      \
        char* dst = sm + SM_EB + (b) * EBUF_FULL;                                 \
        _Pragma("unroll")                                                          \
        for (int j = 0; j < 2; j++) {                                             \
            int q = tid + NT * j;                                                 \
            int code = q >> 3, cc = q & 7;                                        \
            *(uint4*)(dst + code * ROWB + cc * 16) = shh[q];                      \
            *(uint4*)(dst + EBUF_SPLIT + code * ROWB + cc * 16) = sll[q];         \
        }                                                                          \
    } while (0)

    COPY_E(0, 0);

    // best/sec tracked in HALF-dist units (acc = esq/2 - dot = dist/2)
    float best[2], sec[2];
    int idx[2];
#pragma unroll
    for (int s = 0; s < 2; s++) { best[s] = 3.4e38f; sec[s] = 3.4e38f; idx[s] = 0; }
    __syncthreads();

    const uint32_t lrow = (lane & 7) * ROWB;                       // ldmatrix row addr part
    const uint32_t ldb = ((lane >> 4) & 1) * 32 + ((lane >> 3) & 1) * 16;  // mat -> d bytes

    for (int ch = 0; ch < 16; ch++) {
        if (ch < 15) COPY_E(ch + 1, (ch + 1) & 1);
        const uint32_t ebh = sbase + SM_EB + (ch & 1) * EBUF_FULL;
        const uint32_t ebl = ebh + EBUF_SPLIT;

        // init acc with esq/2 (esq folded into GEMM; E is negated)
        float acc[8][4];
#pragma unroll
        for (int nt = 0; nt < 8; nt++) {
            float2 p = *(const float2*)(esq2_s + ch * 64 + nt * 8 + c4 * 2);
            acc[nt][0] = p.x; acc[nt][1] = p.y;
            acc[nt][2] = p.x; acc[nt][3] = p.y;
        }

        // mainloop: nt-groups of 4, MMAs k-major/nt-inner -> same-acc dep distance = 4
#pragma unroll
        for (int hf = 0; hf < 2; hf++) {
            const int nb = hf * 4;
            const uint32_t base_off = nb * (8 * ROWB) + lrow + ldb;
            {   // hi split
                uint32_t B[4][8];
#pragma unroll
                for (int t = 0; t < 4; t++) {
                    uint32_t roff = ebh + base_off + t * (8 * ROWB);
                    ldsm4(B[t][0], B[t][1], B[t][2], B[t][3], roff);
                    ldsm4(B[t][4], B[t][5], B[t][6], B[t][7], roff + 64);
                }
#pragma unroll
                for (int k = 0; k < 4; k++)
#pragma unroll
                    for (int t = 0; t < 4; t++)
                        mma16816(acc[nb + t], ah[k][0], ah[k][1], ah[k][2], ah[k][3],
                                 B[t][2 * k], B[t][2 * k + 1]);
            }
            {   // lo split
                uint32_t B[4][8];
#pragma unroll
                for (int t = 0; t < 4; t++) {
                    uint32_t roff = ebl + base_off + t * (8 * ROWB);
                    ldsm4(B[t][0], B[t][1], B[t][2], B[t][3], roff);
                    ldsm4(B[t][4], B[t][5], B[t][6], B[t][7], roff + 64);
                }
#pragma unroll
                for (int k = 0; k < 4; k++)
#pragma unroll
                    for (int t = 0; t < 4; t++)
                        mma16816(acc[nb + t], ah[k][0], ah[k][1], ah[k][2], ah[k][3],
                                 B[t][2 * k], B[t][2 * k + 1]);
            }
        }

        // chunk epilogue: acc IS dist/2; branchless min/argmin (5 fixed-lat instrs/value)
#pragma unroll
        for (int nt = 0; nt < 8; nt++) {
            int c0 = ch * 64 + nt * 8 + c4 * 2;
            float d0 = acc[nt][0], d1 = acc[nt][1];
            float d2 = acc[nt][2], d3 = acc[nt][3];
            sec[0] = fminf(sec[0], fmaxf(best[0], d0));
            idx[0] = (d0 < best[0]) ? c0 : idx[0];
            best[0] = fminf(best[0], d0);
            sec[0] = fminf(sec[0], fmaxf(best[0], d1));
            idx[0] = (d1 < best[0]) ? (c0 + 1) : idx[0];
            best[0] = fminf(best[0], d1);
            sec[1] = fminf(sec[1], fmaxf(best[1], d2));
            idx[1] = (d2 < best[1]) ? c0 : idx[1];
            best[1] = fminf(best[1], d2);
            sec[1] = fminf(sec[1], fmaxf(best[1], d3));
            idx[1] = (d3 < best[1]) ? (c0 + 1) : idx[1];
            best[1] = fminf(best[1], d3);
        }
        __syncthreads();
    }

    // merge across the 4 lanes of each quad (same row, c4 = 0..3)
#pragma unroll
    for (int s = 0; s < 2; s++) {
#pragma unroll
        for (int o = 1; o < 4; o <<= 1) {
            float ob = __shfl_xor_sync(0xffffffffu, best[s], o);
            float os = __shfl_xor_sync(0xffffffffu, sec[s], o);
            int oi = __shfl_xor_sync(0xffffffffu, idx[s], o);
            if (ob < best[s] || (ob == best[s] && oi < idx[s])) {
                sec[s] = fminf(fminf(sec[s], os), best[s]);
                best[s] = ob; idx[s] = oi;
            } else {
                sec[s] = fminf(fminf(sec[s], os), ob);
            }
        }
        int row = rowb + s * 8 + g;
        if (c4 == 0) { rbest[row] = best[s]; rsec[row] = sec[s]; ridx[row] = idx[s]; }
    }
    __syncthreads();

    if (tid < TM) {
        // per-row state (thread = row); convert half-dist -> dist units
        float bd = 2.f * rbest[tid], sd = 2.f * rsec[tid];
        int bi = ridx[tid];

        // deterministic exact-fp32 rescue for ambiguous rows
        bool flagged = (sd - bd < 0.04f);
        unsigned fl = __ballot_sync(0xffffffffu, flagged);
        while (fl) {
            int fr = __ffs(fl) - 1; fl &= fl - 1;
            int rr = wid * 32 + fr;
            const float4* xrr = (const float4*)(X + ((size_t)blockIdx.x * TM + rr) * DC);
            float xv[64];
#pragma unroll
            for (int q = 0; q < 16; q++) {
                float4 v = xrr[q];
                xv[4 * q] = v.x; xv[4 * q + 1] = v.y;
                xv[4 * q + 2] = v.z; xv[4 * q + 3] = v.w;
            }
            float bb = 3.4e38f; int bj = 0;
            for (int c = lane; c < KC; c += 32) {
                const float4* er = (const float4*)(E + (size_t)c * DC);
                float dot = 0.f;
#pragma unroll
                for (int q = 0; q < 16; q++) {
                    float4 e4 = er[q];
                    dot = fmaf(xv[4 * q], e4.x, dot);
                    dot = fmaf(xv[4 * q + 1], e4.y, dot);
                    dot = fmaf(xv[4 * q + 2], e4.z, dot);
                    dot = fmaf(xv[4 * q + 3], e4.w, dot);
                }
                float pd = fmaf(-2.f, dot, 2.f * esq2_s[c]);
                if (pd < bb) { bb = pd; bj = c; }
            }
#pragma unroll
            for (int o = 16; o > 0; o >>= 1) {
                float ov = __shfl_xor_sync(0xffffffffu, bb, o);
                int oi = __shfl_xor_sync(0xffffffffu, bj, o);
                if (ov < bb || (ov == bb && oi < bj)) { bb = ov; bj = oi; }
            }
            if (lane == fr) { bd = bb; bi = bj; }
        }

        // writeout (thread = row), exact X from gmem
        size_t gr = (size_t)blockIdx.x * TM + tid;
        const float4* xr = (const float4*)(X + gr * DC);
        const float4* er = (const float4*)(E + (size_t)bi * DC);
        float4* Zr = (float4*)(oZ + gr * DC);
        float xsq = 0.f, lsum = 0.f;
        atomicAdd(&g_counts[bi], 1.0f);
        float* srow = &g_sums[bi * DC];
#pragma unroll
        for (int q = 0; q < 16; q++) {
            float4 xv4 = xr[q];
            float4 e4 = er[q];
            float d0 = e4.x - xv4.x, d1 = e4.y - xv4.y;
            float d2 = e4.z - xv4.z, d3 = e4.w - xv4.w;
            float4 z;
            z.x = xv4.x + d0; z.y = xv4.y + d1; z.z = xv4.z + d2; z.w = xv4.w + d3;
            Zr[q] = z;
            lsum = fmaf(d0, d0, lsum); lsum = fmaf(d1, d1, lsum);
            lsum = fmaf(d2, d2, lsum); lsum = fmaf(d3, d3, lsum);
            xsq = fmaf(xv4.x, xv4.x, xsq); xsq = fmaf(xv4.y, xv4.y, xsq);
            xsq = fmaf(xv4.z, xv4.z, xsq); xsq = fmaf(xv4.w, xv4.w, xsq);
            atomicAdd(srow + 4 * q + 0, xv4.x);
            atomicAdd(srow + 4 * q + 1, xv4.y);
            atomicAdd(srow + 4 * q + 2, xv4.z);
            atomicAdd(srow + 4 * q + 3, xv4.w);
        }
        oMin[gr] = xsq + bd;
        oArg[gr] = (float)bi;
#pragma unroll
        for (int o = 16; o > 0; o >>= 1) lsum += __shfl_xor_sync(0xffffffffu, lsum, o);
        if (lane == 0) atomicAdd(g_loss, lsum);
    }
}

// ---------------- finalize ----------------
__global__ void vq_fin1(const float* __restrict__ cs_in,
                        float* __restrict__ oCs, float* __restrict__ oLoss) {
    __shared__ float wsum[32];
    __shared__ float Ssh;
    int k = threadIdx.x;
    const float G = 0.99f;
    const float OMG = (float)(1.0 - 0.99);
    float c = G * cs_in[k] + OMG * g_counts[k];

    float s = c;
#pragma unroll
    for (int o = 16; o > 0; o >>= 1) s += __shfl_xor_sync(0xffffffffu, s, o);
    if ((k & 31) == 0) wsum[k >> 5] = s;
    __syncthreads();
    if (k < 32) {
        float t = wsum[k];
#pragma unroll
        for (int o = 16; o > 0; o >>= 1) t += __shfl_xor_sync(0xffffffffu, t, o);
        if (k == 0) Ssh = t;
    }
    __syncthreads();
    float S = Ssh;

    float csa = (c + 1e-9f) / (1.0f + (float)(1e-9 * 1024.0) / S);
    oCs[k] = csa;
    g_csa[k] = csa;
    if (k == 0) oLoss[0] = 0.25f * g_loss[0] / (float)NV;
}

// oEn/oMa offset by +1 float in d_out -> scalar stores only
__global__ void vq_fin2(const float* __restrict__ mavg,
                        float* __restrict__ oEn, float* __restrict__ oMa) {
    const float G = 0.99f;
    const float OMG = (float)(1.0 - 0.99);
    int i4 = blockIdx.x * blockDim.x + threadIdx.x;
    float4 mv = ((const float4*)mavg)[i4];
    float4 sv = ((const float4*)g_sums)[i4];
    float csa = g_csa[i4 >> 4];
    int b = i4 * 4;
    float m0 = G * mv.x + OMG * sv.x;
    float m1 = G * mv.y + OMG * sv.y;
    float m2 = G * mv.z + OMG * sv.z;
    float m3 = G * mv.w + OMG * sv.w;
    oMa[b + 0] = m0;  oEn[b + 0] = m0 / csa;
    oMa[b + 1] = m1;  oEn[b + 1] = m1 / csa;
    oMa[b + 2] = m2;  oEn[b + 2] = m2 / csa;
    oMa[b + 3] = m3;  oEn[b + 3] = m3 / csa;
}

// ---------------- launch ----------------
extern "C" void kernel_launch(void* const* d_in, const int* in_sizes, int n_in,
                              void* d_out, int out_size) {
    const float* X  = (const float*)d_in[0];
    const float* E  = (const float*)d_in[1];
    const float* cs = (const float*)d_in[2];
    const float* ma = (const float*)d_in[3];

    float* o = (float*)d_out;
    float* oZ    = o;
    float* oLoss = o + (size_t)NV * DC;
    float* oArg  = oLoss + 1;
    float* oMin  = oArg + NV;
    float* oEn   = oMin + NV;
    float* oCs   = oEn + (size_t)KC * DC;
    float* oMa   = oCs + KC;

    cudaFuncSetAttribute(vq_main_mma, cudaFuncAttributeMaxDynamicSharedMemorySize, SM_TOTB);

    vq_zero<<<(KC * DC / 4 + KC + 1 + 255) / 256, 256>>>();
    vq_esq<<<(KC + 255) / 256, 256>>>(E);
    vq_esplit<<<KC * DC / 4 / 256, 256>>>(E);
    vq_main_mma<<<NV / TM, NT, SM_TOTB>>>(X, E, oZ, oArg, oMin);
    vq_fin1<<<1, KC>>>(cs, oCs, oLoss);
    vq_fin2<<<KC * DC / 4 / 256, 256>>>(ma, oEn, oMa);
}